// round 3
// baseline (speedup 1.0000x reference)
#include <cuda_runtime.h>
#include <cstdint>

#define NPTS 65536
#define CCH  1024
#define BSEG 256
#define KPAD 512
#define LN_EPS 1e-5f

// ---------------- scratch (no allocations allowed) ----------------
__device__ float g_feat[BSEG * CCH];           // segment-max features (then clamped)
__device__ float g_x[BSEG * 544];              // concat(pf, inf)
__device__ float g_part1[16 * BSEG * 512];     // GEMM1 split-K partials (8 MB, L2-resident)
__device__ float g_part2[2 * 8 * BSEG * 256];  // head GEMM partials [head][kz][m][n] (4 MB)
__device__ int   g_off[BSEG];                  // canonical int32 offsets

// ---------------- fused: offsets canonicalization + feat init + info linear ----------------
__global__ void k_off_init(const void* offs,
                           const float* __restrict__ info,
                           const float* __restrict__ Wi,
                           const float* __restrict__ bi) {
    int b = blockIdx.x;
    int t = threadIdx.x;
    if (b == 1056) {
        __shared__ unsigned okf;
        if (t == 0) okf = 1u;
        __syncthreads();
        const long long* p64 = (const long long*)offs;
        if (t < 128) {  // first 128 int64 slots = 1KB, safe for either dtype
            long long v = p64[t];
            long long prev = t ? p64[t - 1] : 0;
            if (v < 0 || v > (long long)NPTS || v < prev) atomicAnd(&okf, 0u);
        }
        __syncthreads();
        if (okf) g_off[t] = (int)p64[t];
        else     g_off[t] = ((const int*)offs)[t];
        return;
    }
    int idx = b * 256 + t;
    if (idx < BSEG * CCH) {
        g_feat[idx] = __int_as_float(0xFF800000);  // -inf
    } else {
        int j = idx - BSEG * CCH;          // [0, 8192)
        int m = j >> 5;
        int o = j & 31;
        const float* ip = info + m * 3;
        const float* w  = Wi + o * 3;
        g_x[m * 544 + 512 + o] = ip[0] * w[0] + ip[1] * w[1] + ip[2] * w[2] + bi[o];
    }
}

// ---------------- float atomic max (order-independent => deterministic) ----------------
__device__ __forceinline__ void atomicMaxF(float* addr, float v) {
    if (v >= 0.0f) atomicMax((int*)addr, __float_as_int(v));
    else           atomicMin((unsigned int*)addr, __float_as_uint(v));
}

// ---------------- segment max: point-parallel, 128 rows/block ----------------
__global__ void __launch_bounds__(256) k_segmax(const float4* __restrict__ feat) {
    __shared__ int soff[BSEG];
    int tid = threadIdx.x;
    soff[tid] = g_off[tid];
    __syncthreads();

    const int r0 = blockIdx.x * 128;
    int lo = 0, hi = BSEG;
    while (lo < hi) { int mid = (lo + hi) >> 1; if (soff[mid] > r0) hi = mid; else lo = mid + 1; }
    int seg = lo;
    int cur_end = soff[seg];

    const float NEG = __int_as_float(0xFF800000);
    float4 run = make_float4(NEG, NEG, NEG, NEG);
    const float4* p = feat + (size_t)r0 * 256 + tid;

    for (int r = r0; r < r0 + 128; r += 4) {
        float4 v0 = __ldg(p);
        float4 v1 = __ldg(p + 256);
        float4 v2 = __ldg(p + 512);
        float4 v3 = __ldg(p + 768);
        p += 1024;
#pragma unroll
        for (int i = 0; i < 4; i++) {
            float4 v = (i == 0) ? v0 : (i == 1) ? v1 : (i == 2) ? v2 : v3;
            int rr = r + i;
            if (rr >= cur_end) {
                float* d = &g_feat[(size_t)seg * CCH + tid * 4];
                atomicMaxF(d + 0, run.x); atomicMaxF(d + 1, run.y);
                atomicMaxF(d + 2, run.z); atomicMaxF(d + 3, run.w);
                run = make_float4(NEG, NEG, NEG, NEG);
                do { seg++; } while (soff[seg] <= rr);
                cur_end = soff[seg];
            }
            run.x = fmaxf(run.x, v.x); run.y = fmaxf(run.y, v.y);
            run.z = fmaxf(run.z, v.z); run.w = fmaxf(run.w, v.w);
        }
    }
    float* d = &g_feat[(size_t)seg * CCH + tid * 4];
    atomicMaxF(d + 0, run.x); atomicMaxF(d + 1, run.y);
    atomicMaxF(d + 2, run.z); atomicMaxF(d + 3, run.w);
}

// ---------------- clamp short segments, publish features (MLP=4 per thread) ----------------
__global__ void __launch_bounds__(256) k_fixup(float* __restrict__ out) {
    int t = blockIdx.x * 256 + threadIdx.x;  // 0..16383
#pragma unroll
    for (int i = 0; i < 4; i++) {
        int idx = t + i * 16384;             // float4 index, 0..65535
        int m = idx >> 8;
        int len = g_off[m] - (m ? g_off[m - 1] : 0);
        float4 v = ((float4*)g_feat)[idx];
        if (len < KPAD) {
            v.x = fmaxf(v.x, 0.f); v.y = fmaxf(v.y, 0.f);
            v.z = fmaxf(v.z, 0.f); v.w = fmaxf(v.w, 0.f);
        }
        ((float4*)g_feat)[idx] = v;
        ((float4*)out)[idx] = v;
    }
}

// ---------------- fp32 GEMM body: 64(m) x 128(n) tile, BK=8, 8x8 microtile, 128 thr ----------------
// LDS bytes per FMA = 1 (a-loads warp-broadcast), FMA-pipe bound.
__device__ __forceinline__ void gemm_body(const float* __restrict__ A, int lda,
                                          const float* __restrict__ W, int K,
                                          int k0, int kend,
                                          float* __restrict__ Cp, int Nn,
                                          int bm, int bn) {
    __shared__ float As[2][8][64];
    __shared__ float Bs[2][8][128];
    const int tid = threadIdx.x;
    const int tm = (tid >> 4) << 3;    // 0,8,..,56
    const int tn = (tid & 15) << 3;    // 0,8,..,120
    const int ar  = tid >> 1;          // A row 0..63
    const int kq  = (tid & 1) << 2;    // k-quad 0 or 4
    const int br0 = tid >> 1;          // B row 0..63 (and +64)

    float acc[8][8];
#pragma unroll
    for (int i = 0; i < 8; i++)
#pragma unroll
        for (int j = 0; j < 8; j++) acc[i][j] = 0.f;

    float ra[4], rb[8];
    const int ntiles = (kend - k0 + 7) >> 3;

    // prologue: tile 0 -> regs -> smem[0]
    {
        const int kt = k0;
        const float* ap = A + (size_t)(bm + ar) * lda + kt + kq;
#pragma unroll
        for (int u = 0; u < 4; u++) ra[u] = (kt + kq + u < kend) ? ap[u] : 0.f;
#pragma unroll
        for (int q0 = 0; q0 < 2; q0++) {
            const float* wp = W + (size_t)(bn + br0 + q0 * 64) * K + kt + kq;
#pragma unroll
            for (int u = 0; u < 4; u++) rb[q0 * 4 + u] = (kt + kq + u < kend) ? wp[u] : 0.f;
        }
#pragma unroll
        for (int u = 0; u < 4; u++) As[0][kq + u][ar] = ra[u];
#pragma unroll
        for (int q0 = 0; q0 < 2; q0++)
#pragma unroll
            for (int u = 0; u < 4; u++) Bs[0][kq + u][br0 + q0 * 64] = rb[q0 * 4 + u];
    }
    __syncthreads();

    for (int i = 0; i < ntiles; i++) {
        const int s = i & 1;
        if (i + 1 < ntiles) {  // prefetch next tile into registers
            const int kt = k0 + (i + 1) * 8;
            const float* ap = A + (size_t)(bm + ar) * lda + kt + kq;
#pragma unroll
            for (int u = 0; u < 4; u++) ra[u] = (kt + kq + u < kend) ? ap[u] : 0.f;
#pragma unroll
            for (int q0 = 0; q0 < 2; q0++) {
                const float* wp = W + (size_t)(bn + br0 + q0 * 64) * K + kt + kq;
#pragma unroll
                for (int u = 0; u < 4; u++) rb[q0 * 4 + u] = (kt + kq + u < kend) ? wp[u] : 0.f;
            }
        }
#pragma unroll
        for (int kk = 0; kk < 8; kk++) {
            float4 a0 = *(const float4*)&As[s][kk][tm];
            float4 a1 = *(const float4*)&As[s][kk][tm + 4];
            float4 b0 = *(const float4*)&Bs[s][kk][tn];
            float4 b1 = *(const float4*)&Bs[s][kk][tn + 4];
            float av[8] = {a0.x, a0.y, a0.z, a0.w, a1.x, a1.y, a1.z, a1.w};
            float bv[8] = {b0.x, b0.y, b0.z, b0.w, b1.x, b1.y, b1.z, b1.w};
#pragma unroll
            for (int ii = 0; ii < 8; ii++)
#pragma unroll
                for (int jj = 0; jj < 8; jj++) acc[ii][jj] += av[ii] * bv[jj];
        }
        if (i + 1 < ntiles) {  // stage into the other buffer
            const int d = s ^ 1;
#pragma unroll
            for (int u = 0; u < 4; u++) As[d][kq + u][ar] = ra[u];
#pragma unroll
            for (int q0 = 0; q0 < 2; q0++)
#pragma unroll
                for (int u = 0; u < 4; u++) Bs[d][kq + u][br0 + q0 * 64] = rb[q0 * 4 + u];
        }
        __syncthreads();
    }

    float* cp = Cp + (size_t)(bm + tm) * Nn + bn + tn;
#pragma unroll
    for (int i = 0; i < 8; i++) {
        *(float4*)(cp + (size_t)i * Nn)     = make_float4(acc[i][0], acc[i][1], acc[i][2], acc[i][3]);
        *(float4*)(cp + (size_t)i * Nn + 4) = make_float4(acc[i][4], acc[i][5], acc[i][6], acc[i][7]);
    }
}

// GEMM1: (256x1024) @ W1(512x1024)^T, split-K 16 (KC=64, no tail)
__global__ void __launch_bounds__(128) k_gemm1(const float* __restrict__ W1) {
    int kz = blockIdx.z;
    gemm_body(g_feat, CCH, W1, 1024, kz * 64, kz * 64 + 64,
              g_part1 + (size_t)kz * BSEG * 512, 512,
              blockIdx.y * 64, blockIdx.x * 128);
}

// Head GEMMs merged: z<8 -> anchor head, z>=8 -> offset head; split-K 8 (KC=68, 4-wide tail)
__global__ void __launch_bounds__(128) k_gemm_heads(const float* __restrict__ Wa1,
                                                    const float* __restrict__ Wo1) {
    int z = blockIdx.z;
    int head = z >> 3;
    int kz = z & 7;
    const float* W = head ? Wo1 : Wa1;
    float* C = g_part2 + (size_t)head * 8 * BSEG * 256 + (size_t)kz * BSEG * 256;
    int k0 = kz * 68;
    gemm_body(g_x, 544, W, 544, k0, k0 + 68, C, 256,
              blockIdx.y * 64, blockIdx.x * 128);
}

// ---------------- reduce 16 partials + bias + LayerNorm + ReLU -> x[:,0:512] ----------------
__global__ void k_ln1(const float* __restrict__ b1,
                      const float* __restrict__ g1,
                      const float* __restrict__ be1) {
    __shared__ float2 red[256];
    int m = blockIdx.x, t = threadIdx.x;
    float y0 = b1[t], y1 = b1[t + 256];
#pragma unroll
    for (int p = 0; p < 16; p++) {
        const float* pp = g_part1 + ((size_t)p * BSEG + m) * 512;
        y0 += pp[t];
        y1 += pp[t + 256];
    }
    red[t] = make_float2(y0 + y1, y0 * y0 + y1 * y1);
    __syncthreads();
    for (int off = 128; off > 0; off >>= 1) {
        if (t < off) {
            float2 a = red[t], b = red[t + off];
            a.x += b.x; a.y += b.y; red[t] = a;
        }
        __syncthreads();
    }
    float mean = red[0].x * (1.f / 512.f);
    float var  = red[0].y * (1.f / 512.f) - mean * mean;
    float inv  = rsqrtf(var + LN_EPS);
    g_x[m * 544 + t]       = fmaxf((y0 - mean) * inv * g1[t] + be1[t], 0.f);
    g_x[m * 544 + t + 256] = fmaxf((y1 - mean) * inv * g1[t + 256] + be1[t + 256], 0.f);
}

// ---------------- heads: reduce 8 partials/head, dual LN+ReLU, tiny output GEMMs ----------------
__global__ void k_heads(const float* __restrict__ ba1, const float* __restrict__ lnag,
                        const float* __restrict__ lnab, const float* __restrict__ Wa2,
                        const float* __restrict__ ba2,  const float* __restrict__ bo1,
                        const float* __restrict__ lnog, const float* __restrict__ lnob,
                        const float* __restrict__ Wo2,  const float* __restrict__ bo2,
                        float* __restrict__ out) {
    __shared__ float4 red[256];
    __shared__ float sha[256], sho[256];
    int m = blockIdx.x, t = threadIdx.x;
    float ya = ba1[t], yo = bo1[t];
#pragma unroll
    for (int p = 0; p < 8; p++) {
        ya += g_part2[((size_t)p * BSEG + m) * 256 + t];
        yo += g_part2[(size_t)8 * BSEG * 256 + ((size_t)p * BSEG + m) * 256 + t];
    }
    red[t] = make_float4(ya, ya * ya, yo, yo * yo);
    __syncthreads();
    for (int off = 128; off > 0; off >>= 1) {
        if (t < off) {
            float4 a = red[t], b = red[t + off];
            a.x += b.x; a.y += b.y; a.z += b.z; a.w += b.w; red[t] = a;
        }
        __syncthreads();
    }
    float ma = red[0].x * (1.f / 256.f), va = red[0].y * (1.f / 256.f) - ma * ma;
    float mo = red[0].z * (1.f / 256.f), vo = red[0].w * (1.f / 256.f) - mo * mo;
    sha[t] = fmaxf((ya - ma) * rsqrtf(va + LN_EPS) * lnag[t] + lnab[t], 0.f);
    sho[t] = fmaxf((yo - mo) * rsqrtf(vo + LN_EPS) * lnog[t] + lnob[t], 0.f);
    __syncthreads();

    int w = t >> 5, lane = t & 31;
#pragma unroll
    for (int jj = 0; jj < 3; jj++) {
        int oi = w * 3 + jj;  // 0..23
        const float* vec; const float* wr; float bias; float* dst;
        if (oi < 6) {
            vec = sha; wr = Wa2 + (size_t)oi * 256; bias = ba2[oi];
            dst = out + 262144 + m * 6 + oi;
        } else {
            int j = oi - 6;
            vec = sho; wr = Wo2 + (size_t)j * 256; bias = bo2[j];
            dst = out + 262144 + 1536 + m * 18 + j;
        }
        float s = 0.f;
#pragma unroll
        for (int i = 0; i < 8; i++) s += vec[lane + 32 * i] * wr[lane + 32 * i];
#pragma unroll
        for (int sh = 16; sh > 0; sh >>= 1) s += __shfl_down_sync(0xffffffffu, s, sh);
        if (lane == 0) *dst = s + bias;
    }
}

// ---------------- host launcher ----------------
extern "C" void kernel_launch(void* const* d_in, const int* in_sizes, int n_in,
                              void* d_out, int out_size) {
    const float *feat, *info, *W1, *b1, *ln1g, *ln1b, *Wi, *bi;
    const float *Wa1, *ba1, *lnag, *lnab, *Wa2, *ba2;
    const float *Wo1, *bo1, *lnog, *lnob, *Wo2, *bo2;
    const void* offs;

    if (in_sizes[2] == 256) {  // dict order: offsets at index 2
        feat = (const float*)d_in[0];  info = (const float*)d_in[1];  offs = d_in[2];
        W1   = (const float*)d_in[3];  b1   = (const float*)d_in[4];
        ln1g = (const float*)d_in[5];  ln1b = (const float*)d_in[6];
        Wi   = (const float*)d_in[7];  bi   = (const float*)d_in[8];
        Wa1  = (const float*)d_in[9];  ba1  = (const float*)d_in[10];
        lnag = (const float*)d_in[11]; lnab = (const float*)d_in[12];
        Wa2  = (const float*)d_in[13]; ba2  = (const float*)d_in[14];
        Wo1  = (const float*)d_in[15]; bo1  = (const float*)d_in[16];
        lnog = (const float*)d_in[17]; lnob = (const float*)d_in[18];
        Wo2  = (const float*)d_in[19]; bo2  = (const float*)d_in[20];
    } else {                   // signature order: offsets last
        feat = (const float*)d_in[0];  info = (const float*)d_in[1];
        W1   = (const float*)d_in[2];  b1   = (const float*)d_in[3];
        ln1g = (const float*)d_in[4];  ln1b = (const float*)d_in[5];
        Wi   = (const float*)d_in[6];  bi   = (const float*)d_in[7];
        Wa1  = (const float*)d_in[8];  ba1  = (const float*)d_in[9];
        lnag = (const float*)d_in[10]; lnab = (const float*)d_in[11];
        Wa2  = (const float*)d_in[12]; ba2  = (const float*)d_in[13];
        Wo1  = (const float*)d_in[14]; bo1  = (const float*)d_in[15];
        lnog = (const float*)d_in[16]; lnob = (const float*)d_in[17];
        Wo2  = (const float*)d_in[18]; bo2  = (const float*)d_in[19];
        offs = d_in[20];
    }
    float* out = (float*)d_out;

    k_off_init<<<1057, 256>>>(offs, info, Wi, bi);
    k_segmax<<<512, 256>>>((const float4*)feat);
    k_fixup<<<64, 256>>>(out);
    k_gemm1<<<dim3(4, 4, 16), 128>>>(W1);
    k_ln1<<<256, 256>>>(b1, ln1g, ln1b);
    k_gemm_heads<<<dim3(2, 4, 16), 128>>>(Wa1, Wo1);
    k_heads<<<256, 256>>>(ba1, lnag, lnab, Wa2, ba2, bo1, lnog, lnob, Wo2, bo2, out);
}

// round 4
// speedup vs baseline: 1.1162x; 1.1162x over previous
#include <cuda_runtime.h>
#include <cstdint>

#define NPTS 65536
#define CCH  1024
#define BSEG 256
#define KPAD 512
#define LN_EPS 1e-5f

// ---------------- scratch (no allocations allowed) ----------------
__device__ float g_feat[BSEG * CCH];           // raw segment-max (clamp applied at consumers)
__device__ float g_x[BSEG * 544];              // concat(pf, inf)
__device__ float g_part1[16 * BSEG * 512];     // GEMM1 split-K partials (8 MB, L2-resident)
__device__ float g_part2[2 * 16 * BSEG * 256]; // head GEMM partials [head][kz][m][n] (8 MB)
__device__ int   g_off[BSEG];                  // canonical int32 offsets

// ---------------- fused: offsets canonicalization + feat init + info linear ----------------
__global__ void k_off_init(const void* offs,
                           const float* __restrict__ info,
                           const float* __restrict__ Wi,
                           const float* __restrict__ bi) {
    int b = blockIdx.x;
    int t = threadIdx.x;
    if (b == 1056) {
        __shared__ unsigned okf;
        if (t == 0) okf = 1u;
        __syncthreads();
        const long long* p64 = (const long long*)offs;
        if (t < 128) {  // first 128 int64 slots = 1KB, safe for either dtype
            long long v = p64[t];
            long long prev = t ? p64[t - 1] : 0;
            if (v < 0 || v > (long long)NPTS || v < prev) atomicAnd(&okf, 0u);
        }
        __syncthreads();
        if (okf) g_off[t] = (int)p64[t];
        else     g_off[t] = ((const int*)offs)[t];
        return;
    }
    int idx = b * 256 + t;
    if (idx < BSEG * CCH) {
        g_feat[idx] = __int_as_float(0xFF800000);  // -inf (re-poisoned every replay)
    } else {
        int j = idx - BSEG * CCH;          // [0, 8192)
        int m = j >> 5;
        int o = j & 31;
        const float* ip = info + m * 3;
        const float* w  = Wi + o * 3;
        g_x[m * 544 + 512 + o] = ip[0] * w[0] + ip[1] * w[1] + ip[2] * w[2] + bi[o];
    }
}

// ---------------- float atomic max (order-independent => deterministic) ----------------
__device__ __forceinline__ void atomicMaxF(float* addr, float v) {
    if (v >= 0.0f) atomicMax((int*)addr, __float_as_int(v));
    else           atomicMin((unsigned int*)addr, __float_as_uint(v));
}

// ---------------- segment max: point-parallel, 128 rows/block ----------------
__global__ void __launch_bounds__(256) k_segmax(const float4* __restrict__ feat) {
    __shared__ int soff[BSEG];
    int tid = threadIdx.x;
    soff[tid] = g_off[tid];
    __syncthreads();

    const int r0 = blockIdx.x * 128;
    int lo = 0, hi = BSEG;
    while (lo < hi) { int mid = (lo + hi) >> 1; if (soff[mid] > r0) hi = mid; else lo = mid + 1; }
    int seg = lo;
    int cur_end = soff[seg];

    const float NEG = __int_as_float(0xFF800000);
    float4 run = make_float4(NEG, NEG, NEG, NEG);
    const float4* p = feat + (size_t)r0 * 256 + tid;

    for (int r = r0; r < r0 + 128; r += 4) {
        float4 v0 = __ldg(p);
        float4 v1 = __ldg(p + 256);
        float4 v2 = __ldg(p + 512);
        float4 v3 = __ldg(p + 768);
        p += 1024;
#pragma unroll
        for (int i = 0; i < 4; i++) {
            float4 v = (i == 0) ? v0 : (i == 1) ? v1 : (i == 2) ? v2 : v3;
            int rr = r + i;
            if (rr >= cur_end) {
                float* d = &g_feat[(size_t)seg * CCH + tid * 4];
                atomicMaxF(d + 0, run.x); atomicMaxF(d + 1, run.y);
                atomicMaxF(d + 2, run.z); atomicMaxF(d + 3, run.w);
                run = make_float4(NEG, NEG, NEG, NEG);
                do { seg++; } while (soff[seg] <= rr);
                cur_end = soff[seg];
            }
            run.x = fmaxf(run.x, v.x); run.y = fmaxf(run.y, v.y);
            run.z = fmaxf(run.z, v.z); run.w = fmaxf(run.w, v.w);
        }
    }
    float* d = &g_feat[(size_t)seg * CCH + tid * 4];
    atomicMaxF(d + 0, run.x); atomicMaxF(d + 1, run.y);
    atomicMaxF(d + 2, run.z); atomicMaxF(d + 3, run.w);
}

// ---------------- publish clamped features to d_out (gemm1 clamps on its own loads) ----------------
__global__ void __launch_bounds__(256) k_fixup(float* __restrict__ out) {
    int t = blockIdx.x * 256 + threadIdx.x;  // 0..16383
#pragma unroll
    for (int i = 0; i < 4; i++) {
        int idx = t + i * 16384;             // float4 index, 0..65535
        int m = idx >> 8;
        int len = g_off[m] - (m ? g_off[m - 1] : 0);
        float4 v = ((float4*)g_feat)[idx];
        if (len < KPAD) {
            v.x = fmaxf(v.x, 0.f); v.y = fmaxf(v.y, 0.f);
            v.z = fmaxf(v.z, 0.f); v.w = fmaxf(v.w, 0.f);
        }
        ((float4*)out)[idx] = v;
    }
}

// ---------------- fp32 GEMM body: 64(m) x 128(n) tile, BK=16, 8x4 microtile, 256 thr ----------------
// clampA: apply fmaxf(.,0) on A loads for rows whose segment length < KPAD.
template <bool CLAMP_A>
__device__ __forceinline__ void gemm_body(const float* __restrict__ A, int lda,
                                          const float* __restrict__ W, int K,
                                          int k0, int kend,
                                          float* __restrict__ Cp, int Nn,
                                          int bm, int bn) {
    __shared__ float As[2][16][64];
    __shared__ float Bs[2][16][128];
    const int tid = threadIdx.x;
    const int tm = (tid >> 5) << 3;    // warp -> 8-row stripe: 0,8,..,56
    const int tn = (tid & 31) << 2;    // lane -> 4 cols: 0..124
    const int ar  = tid >> 2;          // A row 0..63
    const int akq = (tid & 3) << 2;    // A k-quad 0,4,8,12
    const int br0 = tid >> 2;          // B row 0..63 (and +64)

    bool doclamp = false;
    if (CLAMP_A) {
        int m = bm + ar;
        int len = g_off[m] - (m ? g_off[m - 1] : 0);
        doclamp = (len < KPAD);
    }

    float acc[8][4];
#pragma unroll
    for (int i = 0; i < 8; i++)
#pragma unroll
        for (int j = 0; j < 4; j++) acc[i][j] = 0.f;

    float ra[4], rb[8];
    const int ntiles = (kend - k0 + 15) >> 4;

    // prologue: tile 0 -> regs -> smem[0]
    {
        const int kt = k0;
        const float* ap = A + (size_t)(bm + ar) * lda + kt + akq;
#pragma unroll
        for (int u = 0; u < 4; u++) {
            float v = (kt + akq + u < kend) ? ap[u] : 0.f;
            ra[u] = (CLAMP_A && doclamp) ? fmaxf(v, 0.f) : v;
        }
#pragma unroll
        for (int q0 = 0; q0 < 2; q0++) {
            const float* wp = W + (size_t)(bn + br0 + q0 * 64) * K + kt + akq;
#pragma unroll
            for (int u = 0; u < 4; u++) rb[q0 * 4 + u] = (kt + akq + u < kend) ? wp[u] : 0.f;
        }
#pragma unroll
        for (int u = 0; u < 4; u++) As[0][akq + u][ar] = ra[u];
#pragma unroll
        for (int q0 = 0; q0 < 2; q0++)
#pragma unroll
            for (int u = 0; u < 4; u++) Bs[0][akq + u][br0 + q0 * 64] = rb[q0 * 4 + u];
    }
    __syncthreads();

    for (int i = 0; i < ntiles; i++) {
        const int s = i & 1;
        if (i + 1 < ntiles) {  // prefetch next tile into registers
            const int kt = k0 + (i + 1) * 16;
            const float* ap = A + (size_t)(bm + ar) * lda + kt + akq;
#pragma unroll
            for (int u = 0; u < 4; u++) {
                float v = (kt + akq + u < kend) ? ap[u] : 0.f;
                ra[u] = (CLAMP_A && doclamp) ? fmaxf(v, 0.f) : v;
            }
#pragma unroll
            for (int q0 = 0; q0 < 2; q0++) {
                const float* wp = W + (size_t)(bn + br0 + q0 * 64) * K + kt + akq;
#pragma unroll
                for (int u = 0; u < 4; u++) rb[q0 * 4 + u] = (kt + akq + u < kend) ? wp[u] : 0.f;
            }
        }
#pragma unroll
        for (int kk = 0; kk < 16; kk++) {
            float4 a0 = *(const float4*)&As[s][kk][tm];       // warp-broadcast
            float4 a1 = *(const float4*)&As[s][kk][tm + 4];   // warp-broadcast
            float4 b  = *(const float4*)&Bs[s][kk][tn];
            float av[8] = {a0.x, a0.y, a0.z, a0.w, a1.x, a1.y, a1.z, a1.w};
            float bv[4] = {b.x, b.y, b.z, b.w};
#pragma unroll
            for (int ii = 0; ii < 8; ii++)
#pragma unroll
                for (int jj = 0; jj < 4; jj++) acc[ii][jj] += av[ii] * bv[jj];
        }
        if (i + 1 < ntiles) {  // stage into the other buffer
            const int d = s ^ 1;
#pragma unroll
            for (int u = 0; u < 4; u++) As[d][akq + u][ar] = ra[u];
#pragma unroll
            for (int q0 = 0; q0 < 2; q0++)
#pragma unroll
                for (int u = 0; u < 4; u++) Bs[d][akq + u][br0 + q0 * 64] = rb[q0 * 4 + u];
        }
        __syncthreads();
    }

    float* cp = Cp + (size_t)(bm + tm) * Nn + bn + tn;
#pragma unroll
    for (int i = 0; i < 8; i++)
        *(float4*)(cp + (size_t)i * Nn) = make_float4(acc[i][0], acc[i][1], acc[i][2], acc[i][3]);
}

// GEMM1: (256x1024) @ W1(512x1024)^T, split-K 16 (KC=64), clamp-on-load
__global__ void __launch_bounds__(256) k_gemm1(const float* __restrict__ W1) {
    int kz = blockIdx.z;
    gemm_body<true>(g_feat, CCH, W1, 1024, kz * 64, kz * 64 + 64,
                    g_part1 + (size_t)kz * BSEG * 512, 512,
                    blockIdx.y * 64, blockIdx.x * 128);
}

// Head GEMMs merged: z<16 -> anchor, z>=16 -> offset; split-K 16 (KC=34, 16*34=544 exact)
__global__ void __launch_bounds__(256) k_gemm_heads(const float* __restrict__ Wa1,
                                                    const float* __restrict__ Wo1) {
    int z = blockIdx.z;
    int head = z >> 4;
    int kz = z & 15;
    const float* W = head ? Wo1 : Wa1;
    float* C = g_part2 + (size_t)head * 16 * BSEG * 256 + (size_t)kz * BSEG * 256;
    int k0 = kz * 34;
    gemm_body<false>(g_x, 544, W, 544, k0, k0 + 34, C, 256,
                     blockIdx.y * 64, blockIdx.x * 128);
}

// ---------------- reduce 16 partials + bias + LayerNorm + ReLU -> x[:,0:512] ----------------
__global__ void k_ln1(const float* __restrict__ b1,
                      const float* __restrict__ g1,
                      const float* __restrict__ be1) {
    __shared__ float2 red[256];
    int m = blockIdx.x, t = threadIdx.x;
    float y0 = b1[t], y1 = b1[t + 256];
#pragma unroll
    for (int p = 0; p < 16; p++) {
        const float* pp = g_part1 + ((size_t)p * BSEG + m) * 512;
        y0 += pp[t];
        y1 += pp[t + 256];
    }
    red[t] = make_float2(y0 + y1, y0 * y0 + y1 * y1);
    __syncthreads();
    for (int off = 128; off > 0; off >>= 1) {
        if (t < off) {
            float2 a = red[t], b = red[t + off];
            a.x += b.x; a.y += b.y; red[t] = a;
        }
        __syncthreads();
    }
    float mean = red[0].x * (1.f / 512.f);
    float var  = red[0].y * (1.f / 512.f) - mean * mean;
    float inv  = rsqrtf(var + LN_EPS);
    g_x[m * 544 + t]       = fmaxf((y0 - mean) * inv * g1[t] + be1[t], 0.f);
    g_x[m * 544 + t + 256] = fmaxf((y1 - mean) * inv * g1[t + 256] + be1[t + 256], 0.f);
}

// ---------------- heads: reduce 16 partials/head, dual LN+ReLU, tiny output GEMMs ----------------
__global__ void k_heads(const float* __restrict__ ba1, const float* __restrict__ lnag,
                        const float* __restrict__ lnab, const float* __restrict__ Wa2,
                        const float* __restrict__ ba2,  const float* __restrict__ bo1,
                        const float* __restrict__ lnog, const float* __restrict__ lnob,
                        const float* __restrict__ Wo2,  const float* __restrict__ bo2,
                        float* __restrict__ out) {
    __shared__ float4 red[256];
    __shared__ float sha[256], sho[256];
    int m = blockIdx.x, t = threadIdx.x;
    float ya = ba1[t], yo = bo1[t];
#pragma unroll
    for (int p = 0; p < 16; p++) {
        ya += g_part2[((size_t)p * BSEG + m) * 256 + t];
        yo += g_part2[(size_t)16 * BSEG * 256 + ((size_t)p * BSEG + m) * 256 + t];
    }
    red[t] = make_float4(ya, ya * ya, yo, yo * yo);
    __syncthreads();
    for (int off = 128; off > 0; off >>= 1) {
        if (t < off) {
            float4 a = red[t], b = red[t + off];
            a.x += b.x; a.y += b.y; a.z += b.z; a.w += b.w; red[t] = a;
        }
        __syncthreads();
    }
    float ma = red[0].x * (1.f / 256.f), va = red[0].y * (1.f / 256.f) - ma * ma;
    float mo = red[0].z * (1.f / 256.f), vo = red[0].w * (1.f / 256.f) - mo * mo;
    sha[t] = fmaxf((ya - ma) * rsqrtf(va + LN_EPS) * lnag[t] + lnab[t], 0.f);
    sho[t] = fmaxf((yo - mo) * rsqrtf(vo + LN_EPS) * lnog[t] + lnob[t], 0.f);
    __syncthreads();

    int w = t >> 5, lane = t & 31;
#pragma unroll
    for (int jj = 0; jj < 3; jj++) {
        int oi = w * 3 + jj;  // 0..23
        const float* vec; const float* wr; float bias; float* dst;
        if (oi < 6) {
            vec = sha; wr = Wa2 + (size_t)oi * 256; bias = ba2[oi];
            dst = out + 262144 + m * 6 + oi;
        } else {
            int j = oi - 6;
            vec = sho; wr = Wo2 + (size_t)j * 256; bias = bo2[j];
            dst = out + 262144 + 1536 + m * 18 + j;
        }
        float s = 0.f;
#pragma unroll
        for (int i = 0; i < 8; i++) s += vec[lane + 32 * i] * wr[lane + 32 * i];
#pragma unroll
        for (int sh = 16; sh > 0; sh >>= 1) s += __shfl_down_sync(0xffffffffu, s, sh);
        if (lane == 0) *dst = s + bias;
    }
}

// ---------------- host launcher ----------------
extern "C" void kernel_launch(void* const* d_in, const int* in_sizes, int n_in,
                              void* d_out, int out_size) {
    const float *feat, *info, *W1, *b1, *ln1g, *ln1b, *Wi, *bi;
    const float *Wa1, *ba1, *lnag, *lnab, *Wa2, *ba2;
    const float *Wo1, *bo1, *lnog, *lnob, *Wo2, *bo2;
    const void* offs;

    if (in_sizes[2] == 256) {  // dict order: offsets at index 2
        feat = (const float*)d_in[0];  info = (const float*)d_in[1];  offs = d_in[2];
        W1   = (const float*)d_in[3];  b1   = (const float*)d_in[4];
        ln1g = (const float*)d_in[5];  ln1b = (const float*)d_in[6];
        Wi   = (const float*)d_in[7];  bi   = (const float*)d_in[8];
        Wa1  = (const float*)d_in[9];  ba1  = (const float*)d_in[10];
        lnag = (const float*)d_in[11]; lnab = (const float*)d_in[12];
        Wa2  = (const float*)d_in[13]; ba2  = (const float*)d_in[14];
        Wo1  = (const float*)d_in[15]; bo1  = (const float*)d_in[16];
        lnog = (const float*)d_in[17]; lnob = (const float*)d_in[18];
        Wo2  = (const float*)d_in[19]; bo2  = (const float*)d_in[20];
    } else {                   // signature order: offsets last
        feat = (const float*)d_in[0];  info = (const float*)d_in[1];
        W1   = (const float*)d_in[2];  b1   = (const float*)d_in[3];
        ln1g = (const float*)d_in[4];  ln1b = (const float*)d_in[5];
        Wi   = (const float*)d_in[6];  bi   = (const float*)d_in[7];
        Wa1  = (const float*)d_in[8];  ba1  = (const float*)d_in[9];
        lnag = (const float*)d_in[10]; lnab = (const float*)d_in[11];
        Wa2  = (const float*)d_in[12]; ba2  = (const float*)d_in[13];
        Wo1  = (const float*)d_in[14]; bo1  = (const float*)d_in[15];
        lnog = (const float*)d_in[16]; lnob = (const float*)d_in[17];
        Wo2  = (const float*)d_in[18]; bo2  = (const float*)d_in[19];
        offs = d_in[20];
    }
    float* out = (float*)d_out;

    k_off_init<<<1057, 256>>>(offs, info, Wi, bi);
    k_segmax<<<512, 256>>>((const float4*)feat);
    k_gemm1<<<dim3(4, 4, 16), 256>>>(W1);      // clamps A inline
    k_fixup<<<64, 256>>>(out);                 // publish features to d_out
    k_ln1<<<256, 256>>>(b1, ln1g, ln1b);
    k_gemm_heads<<<dim3(2, 4, 32), 256>>>(Wa1, Wo1);
    k_heads<<<256, 256>>>(ba1, lnag, lnab, Wa2, ba2, bo1, lnog, lnob, Wo2, bo2, out);
}